// round 1
// baseline (speedup 1.0000x reference)
#include <cuda_runtime.h>

#define BB 4
#define SS 2048
#define FF 1024
#define HH 16
#define DD 64

// Scratch (allocation-free requirement -> __device__ globals)
__device__ float g_qh[8388608];   // [B,H,S,D]
__device__ float g_kh[8388608];   // [B,H,S,D]
__device__ float g_vh[8388608];   // [B,H,S,D]
__device__ float g_ctx[8388608];  // [B,S,F]

// ---------------------------------------------------------------------------
// NT GEMM: C[M,N] = A[M,K] @ W[N,K]^T + bias, optional ReLU, optional
// head-split output layout ([B,H,S,D] instead of [M,N]).
// 64x64 tile, BK=16, 256 threads, 4x4 micro-tile per thread.
// ---------------------------------------------------------------------------
template <bool SPLIT, bool RELU>
__global__ __launch_bounds__(256) void gemm_nt(
    const float* __restrict__ A, const float* __restrict__ W,
    const float* __restrict__ bias, float* __restrict__ C, int K)
{
    __shared__ float As[16][64];
    __shared__ float Ws[16][64];

    const int tid = threadIdx.x;
    const int tx = tid & 15;
    const int ty = tid >> 4;
    const int m0 = blockIdx.y * 64;
    const int n0 = blockIdx.x * 64;
    const int lm = tid >> 2;          // 0..63 tile row
    const int lk = (tid & 3) << 2;    // 0,4,8,12 k offset

    float acc[4][4];
#pragma unroll
    for (int i = 0; i < 4; i++)
#pragma unroll
        for (int j = 0; j < 4; j++) acc[i][j] = 0.f;

    const float* Aptr = A + (size_t)(m0 + lm) * K + lk;
    const float* Wptr = W + (size_t)(n0 + lm) * K + lk;

    for (int k0 = 0; k0 < K; k0 += 16) {
        float4 a = *(const float4*)(Aptr + k0);
        float4 w = *(const float4*)(Wptr + k0);
        As[lk + 0][lm] = a.x; As[lk + 1][lm] = a.y;
        As[lk + 2][lm] = a.z; As[lk + 3][lm] = a.w;
        Ws[lk + 0][lm] = w.x; Ws[lk + 1][lm] = w.y;
        Ws[lk + 2][lm] = w.z; Ws[lk + 3][lm] = w.w;
        __syncthreads();
#pragma unroll
        for (int kk = 0; kk < 16; ++kk) {
            float4 ra = *(const float4*)&As[kk][ty << 2];
            float4 rb = *(const float4*)&Ws[kk][tx << 2];
            float av[4] = {ra.x, ra.y, ra.z, ra.w};
            float bv[4] = {rb.x, rb.y, rb.z, rb.w};
#pragma unroll
            for (int i = 0; i < 4; i++)
#pragma unroll
                for (int j = 0; j < 4; j++)
                    acc[i][j] += av[i] * bv[j];
        }
        __syncthreads();
    }

#pragma unroll
    for (int j = 0; j < 4; j++) {
        int n = n0 + (tx << 2) + j;
        float bval = bias[n];
#pragma unroll
        for (int i = 0; i < 4; i++) {
            int m = m0 + (ty << 2) + i;
            float val = acc[i][j] + bval;
            if (RELU) val = val > 0.f ? val : 0.f;
            if (SPLIT) {
                int b = m >> 11;       // m / 2048
                int s = m & 2047;
                int h = n >> 6;        // n / 64
                int d = n & 63;
                C[((((size_t)b * HH + h) * SS) + s) * DD + d] = val;
            } else {
                C[(size_t)m * FF + n] = val;
            }
        }
    }
}

// ---------------------------------------------------------------------------
// scores[b,h,q,k] = (qh[b,h,q,:] . kh[b,h,k,:]) / 8   (D=64, single K pass)
// ---------------------------------------------------------------------------
__global__ __launch_bounds__(256) void scores_kernel(
    const float* __restrict__ qh, const float* __restrict__ kh,
    float* __restrict__ attn)
{
    __shared__ float Qs[64][64];
    __shared__ float Ks[64][64];

    const int bh = blockIdx.z;
    const int m0 = blockIdx.y * 64;
    const int n0 = blockIdx.x * 64;
    const float* Q  = qh + (size_t)bh * SS * DD;
    const float* Kp = kh + (size_t)bh * SS * DD;
    const int tid = threadIdx.x;

#pragma unroll
    for (int i = 0; i < 4; i++) {
        int f = tid + i * 256;        // float4 index, 1024 total
        int r = f >> 4;               // 16 float4 per 64-elem row
        int c = (f & 15) << 2;
        float4 qv = *(const float4*)(Q + (size_t)(m0 + r) * DD + c);
        Qs[c + 0][r] = qv.x; Qs[c + 1][r] = qv.y;
        Qs[c + 2][r] = qv.z; Qs[c + 3][r] = qv.w;
        float4 kv = *(const float4*)(Kp + (size_t)(n0 + r) * DD + c);
        Ks[c + 0][r] = kv.x; Ks[c + 1][r] = kv.y;
        Ks[c + 2][r] = kv.z; Ks[c + 3][r] = kv.w;
    }
    __syncthreads();

    const int tx = tid & 15;
    const int ty = tid >> 4;
    float acc[4][4] = {};
#pragma unroll
    for (int kk = 0; kk < 64; ++kk) {
        float4 ra = *(const float4*)&Qs[kk][ty << 2];
        float4 rb = *(const float4*)&Ks[kk][tx << 2];
        float av[4] = {ra.x, ra.y, ra.z, ra.w};
        float bv[4] = {rb.x, rb.y, rb.z, rb.w};
#pragma unroll
        for (int i = 0; i < 4; i++)
#pragma unroll
            for (int j = 0; j < 4; j++)
                acc[i][j] += av[i] * bv[j];
    }

    float* Ao = attn + ((size_t)bh * SS + m0) * SS + n0;
#pragma unroll
    for (int i = 0; i < 4; i++)
#pragma unroll
        for (int j = 0; j < 4; j++)
            Ao[(size_t)((ty << 2) + i) * SS + (tx << 2) + j] = acc[i][j] * 0.125f;
}

// ---------------------------------------------------------------------------
// In-place row softmax over rows of length 2048. One block (256 thr) per row.
// ---------------------------------------------------------------------------
__global__ __launch_bounds__(256) void softmax_kernel(float* __restrict__ attn)
{
    const size_t row = blockIdx.x;
    float* p = attn + row * SS;
    const int t = threadIdx.x;
    __shared__ float red[8];

    float v[8];
    float mx = -1e30f;
#pragma unroll
    for (int i = 0; i < 8; i++) {
        v[i] = p[t + i * 256];
        mx = fmaxf(mx, v[i]);
    }
#pragma unroll
    for (int o = 16; o > 0; o >>= 1)
        mx = fmaxf(mx, __shfl_xor_sync(0xffffffffu, mx, o));
    if ((t & 31) == 0) red[t >> 5] = mx;
    __syncthreads();
    mx = red[0];
#pragma unroll
    for (int w = 1; w < 8; w++) mx = fmaxf(mx, red[w]);

    float sum = 0.f;
#pragma unroll
    for (int i = 0; i < 8; i++) {
        v[i] = __expf(v[i] - mx);
        sum += v[i];
    }
#pragma unroll
    for (int o = 16; o > 0; o >>= 1)
        sum += __shfl_xor_sync(0xffffffffu, sum, o);
    __syncthreads();
    if ((t & 31) == 0) red[t >> 5] = sum;
    __syncthreads();
    sum = red[0];
#pragma unroll
    for (int w = 1; w < 8; w++) sum += red[w];

    float inv = 1.0f / sum;
#pragma unroll
    for (int i = 0; i < 8; i++) p[t + i * 256] = v[i] * inv;
}

// ---------------------------------------------------------------------------
// ctx[b, s, h*64+d] = sum_j attn[b,h,s,j] * vh[b,h,j,d]
// Per (b,h): [2048 x 64] = [2048 x 2048] @ [2048 x 64]. BK=32.
// ---------------------------------------------------------------------------
__global__ __launch_bounds__(256) void ctx_kernel(
    const float* __restrict__ attn, const float* __restrict__ vh,
    float* __restrict__ ctx)
{
    __shared__ float As[32][64];
    __shared__ float Vs[32][64];

    const int bh = blockIdx.z;
    const int b = bh >> 4;
    const int h = bh & 15;
    const int m0 = blockIdx.y * 64;
    const float* Ap = attn + (size_t)bh * SS * SS;
    const float* Vp = vh + (size_t)bh * SS * DD;
    const int tid = threadIdx.x;
    const int tx = tid & 15;
    const int ty = tid >> 4;

    float acc[4][4] = {};

    for (int k0 = 0; k0 < SS; k0 += 32) {
#pragma unroll
        for (int i = 0; i < 2; i++) {
            int f = tid + i * 256;    // 512 float4 total per tile
            // attn tile: 64 rows x 32 cols -> 8 float4/row
            int r = f >> 3;
            int c = (f & 7) << 2;
            float4 a = *(const float4*)(Ap + (size_t)(m0 + r) * SS + k0 + c);
            As[c + 0][r] = a.x; As[c + 1][r] = a.y;
            As[c + 2][r] = a.z; As[c + 3][r] = a.w;
            // vh tile: 32 rows x 64 cols -> 16 float4/row
            int r2 = f >> 4;
            int c2 = (f & 15) << 2;
            float4 vv = *(const float4*)(Vp + (size_t)(k0 + r2) * DD + c2);
            *(float4*)&Vs[r2][c2] = vv;
        }
        __syncthreads();
#pragma unroll
        for (int kk = 0; kk < 32; ++kk) {
            float4 ra = *(const float4*)&As[kk][ty << 2];
            float4 rb = *(const float4*)&Vs[kk][tx << 2];
            float av[4] = {ra.x, ra.y, ra.z, ra.w};
            float bv[4] = {rb.x, rb.y, rb.z, rb.w};
#pragma unroll
            for (int i = 0; i < 4; i++)
#pragma unroll
                for (int j = 0; j < 4; j++)
                    acc[i][j] += av[i] * bv[j];
        }
        __syncthreads();
    }

#pragma unroll
    for (int i = 0; i < 4; i++) {
        int m = m0 + (ty << 2) + i;
#pragma unroll
        for (int j = 0; j < 4; j++) {
            int n = (tx << 2) + j;
            ctx[((size_t)b * SS + m) * FF + h * DD + n] = acc[i][j];
        }
    }
}

// ---------------------------------------------------------------------------
extern "C" void kernel_launch(void* const* d_in, const int* in_sizes, int n_in,
                              void* d_out, int out_size)
{
    const float* q    = (const float*)d_in[0];
    const float* k    = (const float*)d_in[1];
    const float* v    = (const float*)d_in[2];
    const float* wq_w = (const float*)d_in[3];
    const float* wq_b = (const float*)d_in[4];
    const float* wk_w = (const float*)d_in[5];
    const float* wk_b = (const float*)d_in[6];
    const float* wv_w = (const float*)d_in[7];
    const float* wv_b = (const float*)d_in[8];
    const float* fc_w = (const float*)d_in[9];
    const float* fc_b = (const float*)d_in[10];

    float* out  = (float*)d_out;
    float* attn = out + (size_t)BB * SS * FF;   // out first, then attn

    float *qh, *kh, *vh, *ctx;
    cudaGetSymbolAddress((void**)&qh,  g_qh);
    cudaGetSymbolAddress((void**)&kh,  g_kh);
    cudaGetSymbolAddress((void**)&vh,  g_vh);
    cudaGetSymbolAddress((void**)&ctx, g_ctx);

    dim3 gProj(FF / 64, (BB * SS) / 64);   // (16, 128)
    gemm_nt<true, false><<<gProj, 256>>>(q, wq_w, wq_b, qh, FF);
    gemm_nt<true, false><<<gProj, 256>>>(k, wk_w, wk_b, kh, FF);
    gemm_nt<true, false><<<gProj, 256>>>(v, wv_w, wv_b, vh, FF);

    dim3 gS(SS / 64, SS / 64, BB * HH);    // (32, 32, 64)
    scores_kernel<<<gS, 256>>>(qh, kh, attn);

    softmax_kernel<<<(unsigned)((size_t)BB * HH * SS), 256>>>(attn);

    dim3 gC(1, SS / 64, BB * HH);          // (1, 32, 64)
    ctx_kernel<<<gC, 256>>>(attn, vh, ctx);

    gemm_nt<false, true><<<gProj, 256>>>(ctx, fc_w, fc_b, out, FF);
}

// round 4
// speedup vs baseline: 2.3084x; 2.3084x over previous
#include <cuda_runtime.h>
#include <cuda_bf16.h>
#include <cstdint>

#define BB 4
#define SS 2048
#define FF 1024
#define HH 16
#define DD 64

// Scratch (allocation-free requirement -> __device__ globals)
__device__ float g_qh[BB*HH*SS*DD];   // [B,H,S,D]
__device__ float g_kh[BB*HH*SS*DD];   // [B,H,S,D]
__device__ float g_vt[BB*HH*DD*SS];   // [B,H,D,S]  (V transposed)
__device__ float g_ctx[BB*SS*FF];     // [B,S,F]

// ---------------------------------------------------------------------------
__device__ __forceinline__ uint32_t smem_u32(const void* p) {
    uint32_t a;
    asm("{ .reg .u64 t; cvta.to.shared.u64 t, %1; cvt.u32.u64 %0, t; }"
        : "=r"(a) : "l"(p));
    return a;
}

__device__ __forceinline__ void ldsm4(uint32_t* r, uint32_t addr) {
    asm volatile("ldmatrix.sync.aligned.m8n8.x4.shared.b16 {%0,%1,%2,%3}, [%4];"
                 : "=r"(r[0]), "=r"(r[1]), "=r"(r[2]), "=r"(r[3]) : "r"(addr));
}

__device__ __forceinline__ void mma16816(float* c, const uint32_t* a,
                                         uint32_t b0, uint32_t b1) {
    asm volatile(
        "mma.sync.aligned.m16n8k16.row.col.f32.bf16.bf16.f32 "
        "{%0,%1,%2,%3}, {%4,%5,%6,%7}, {%8,%9}, {%0,%1,%2,%3};"
        : "+f"(c[0]), "+f"(c[1]), "+f"(c[2]), "+f"(c[3])
        : "r"(a[0]), "r"(a[1]), "r"(a[2]), "r"(a[3]), "r"(b0), "r"(b1));
}

__device__ __forceinline__ uint32_t packbf(float a, float b) {
    __nv_bfloat162 t = __floats2bfloat162_rn(a, b);
    return *reinterpret_cast<uint32_t*>(&t);
}

// split float4 into bf16-hi pair-words and bf16-lo pair-words
__device__ __forceinline__ void split_pack(float4 v, uint2& hi, uint2& lo) {
    __nv_bfloat16 hx = __float2bfloat16(v.x);
    __nv_bfloat16 hy = __float2bfloat16(v.y);
    __nv_bfloat16 hz = __float2bfloat16(v.z);
    __nv_bfloat16 hw = __float2bfloat16(v.w);
    hi.x = packbf(v.x, v.y);
    hi.y = packbf(v.z, v.w);
    lo.x = packbf(v.x - __bfloat162float(hx), v.y - __bfloat162float(hy));
    lo.y = packbf(v.z - __bfloat162float(hz), v.w - __bfloat162float(hw));
}

// ---------------------------------------------------------------------------
// 3xBF16 mma.sync NT-GEMM.  STAGE:
//  0: proj Q/K : D[8192,1024] = A @ W^T + b -> split-head [B,H,S,D]
//  1: proj V   : same, written transposed [B,H,D,S]
//  2: scores   : per bh: D[2048,2048] = qh @ kh^T * 0.125
//  3: ctx      : per bh: D[2048,64] = attn @ vt^T -> ctx [B,S,F]
//  4: fc       : D[8192,1024] = ctx @ fcw^T + b, ReLU
// ---------------------------------------------------------------------------
template <int STAGE>
__global__ __launch_bounds__(256) void mma_gemm(
    const float* __restrict__ A, const float* __restrict__ B,
    const float* __restrict__ bias, float* __restrict__ Dst)
{
    constexpr int NT   = (STAGE == 3) ? 64 : 128;
    constexpr int KTOT = (STAGE == 2) ? 64 : ((STAGE == 3) ? 2048 : 1024);
    constexpr int KC   = KTOT / 32;
    constexpr int LDA  = (STAGE == 2) ? 64 : ((STAGE == 3) ? 2048 : 1024);
    constexpr int LDB  = (STAGE == 2) ? 64 : ((STAGE == 3) ? 2048 : 1024);
    constexpr int WN     = NT / 2;       // cols per warp
    constexpr int NPAIRS = WN / 16;      // 4 or 2
    constexpr int NTILES = 2 * NPAIRS;   // 8 or 4
    constexpr int PAD = 40;              // halves per row (80B: conflict-free LDSM)

    __shared__ __align__(16) uint16_t As_h[128 * PAD];
    __shared__ __align__(16) uint16_t As_l[128 * PAD];
    __shared__ __align__(16) uint16_t Bs_h[NT * PAD];
    __shared__ __align__(16) uint16_t Bs_l[NT * PAD];

    const int tid  = threadIdx.x;
    const int wid  = tid >> 5;
    const int lane = tid & 31;
    const int warp_m = wid >> 1;
    const int warp_n = wid & 1;

    const int m0 = blockIdx.y * 128;
    const int n0 = blockIdx.x * NT;
    const int bh = blockIdx.z;

    const float* Ap;
    const float* Bp;
    if constexpr (STAGE == 2) {
        Ap = A + (size_t)bh * SS * DD + (size_t)m0 * LDA;
        Bp = B + (size_t)bh * SS * DD + (size_t)n0 * LDB;
    } else if constexpr (STAGE == 3) {
        Ap = A + (size_t)bh * SS * SS + (size_t)m0 * LDA;
        Bp = B + (size_t)bh * DD * SS;
    } else {
        Ap = A + (size_t)m0 * LDA;
        Bp = B + (size_t)n0 * LDB;
    }

    float acc[2][NTILES][4];
#pragma unroll
    for (int mt = 0; mt < 2; ++mt)
#pragma unroll
        for (int nt = 0; nt < NTILES; ++nt)
#pragma unroll
            for (int i = 0; i < 4; ++i) acc[mt][nt][i] = 0.f;

    for (int ch = 0; ch < KC; ++ch) {
        const int k0 = ch * 32;
        if (ch) __syncthreads();

        // ---- stage A tile: 128 rows x 32 f32 -> bf16 hi/lo ----
#pragma unroll
        for (int i = 0; i < 4; ++i) {
            int f = tid + i * 256;
            int r = f >> 3, c = (f & 7) << 2;
            float4 v = *(const float4*)(Ap + (size_t)r * LDA + k0 + c);
            uint2 hi, lo;
            split_pack(v, hi, lo);
            *(uint2*)&As_h[r * PAD + c] = hi;
            *(uint2*)&As_l[r * PAD + c] = lo;
        }
        // ---- stage B tile: NT rows x 32 f32 ----
#pragma unroll
        for (int i = 0; i < NT / 32; ++i) {
            int f = tid + i * 256;
            int r = f >> 3, c = (f & 7) << 2;
            float4 v = *(const float4*)(Bp + (size_t)r * LDB + k0 + c);
            uint2 hi, lo;
            split_pack(v, hi, lo);
            *(uint2*)&Bs_h[r * PAD + c] = hi;
            *(uint2*)&Bs_l[r * PAD + c] = lo;
        }
        __syncthreads();

#pragma unroll
        for (int ks = 0; ks < 2; ++ks) {
            const int kcol = ks * 16 + (lane >> 4) * 8;
            uint32_t ah[2][4], al[2][4];
#pragma unroll
            for (int mt = 0; mt < 2; ++mt) {
                int row = warp_m * 32 + mt * 16 + (lane & 15);
                ldsm4(ah[mt], smem_u32(&As_h[row * PAD + kcol]));
                ldsm4(al[mt], smem_u32(&As_l[row * PAD + kcol]));
            }
#pragma unroll
            for (int np = 0; np < NPAIRS; ++np) {
                int nrow = warp_n * WN + np * 16 + (lane & 15);
                uint32_t bh4[4], bl4[4];
                ldsm4(bh4, smem_u32(&Bs_h[nrow * PAD + kcol]));
                ldsm4(bl4, smem_u32(&Bs_l[nrow * PAD + kcol]));
#pragma unroll
                for (int mt = 0; mt < 2; ++mt) {
#pragma unroll
                    for (int sub = 0; sub < 2; ++sub) {
                        float* c = acc[mt][np * 2 + sub];
                        mma16816(c, ah[mt], bh4[sub], bh4[sub + 2]);  // hh
                        mma16816(c, ah[mt], bl4[sub], bl4[sub + 2]);  // hl
                        mma16816(c, al[mt], bh4[sub], bh4[sub + 2]);  // lh
                    }
                }
            }
        }
    }

    // ---- epilogue ----
    const int g = lane >> 2;
    const int j = (lane & 3) << 1;
    const int m_base = m0 + warp_m * 32;
    const int n_base = n0 + warp_n * WN;

#pragma unroll
    for (int mt = 0; mt < 2; ++mt) {
#pragma unroll
        for (int nt = 0; nt < NTILES; ++nt) {
#pragma unroll
            for (int e = 0; e < 4; ++e) {
                int row = m_base + mt * 16 + g + (e >> 1) * 8;
                int col = n_base + nt * 8 + j + (e & 1);
                float val = acc[mt][nt][e];
                if constexpr (STAGE == 0) {
                    val += bias[col];
                    int b = row >> 11, s = row & 2047, h = col >> 6, d = col & 63;
                    Dst[((((size_t)b * HH + h) * SS) + s) * DD + d] = val;
                } else if constexpr (STAGE == 1) {
                    val += bias[col];
                    int b = row >> 11, s = row & 2047, h = col >> 6, d = col & 63;
                    Dst[((((size_t)b * HH + h) * DD) + d) * SS + s] = val;
                } else if constexpr (STAGE == 2) {
                    Dst[((size_t)bh * SS + row) * SS + col] = val * 0.125f;
                } else if constexpr (STAGE == 3) {
                    // row is s within this (b,h) block; batch/head come from bh.
                    int b = bh >> 4, h = bh & 15, s = row;
                    Dst[((size_t)b * SS + s) * FF + h * DD + col] = val;
                } else {
                    val += bias[col];
                    Dst[(size_t)row * FF + col] = fmaxf(val, 0.f);
                }
            }
        }
    }
}

// ---------------------------------------------------------------------------
// In-place row softmax over rows of length 2048. One block (256 thr) per row.
// ---------------------------------------------------------------------------
__global__ __launch_bounds__(256) void softmax_kernel(float* __restrict__ attn)
{
    const size_t row = blockIdx.x;
    float* p = attn + row * SS;
    const int t = threadIdx.x;
    __shared__ float red[8];

    float v[8];
    float mx = -1e30f;
#pragma unroll
    for (int i = 0; i < 8; i++) {
        v[i] = p[t + i * 256];
        mx = fmaxf(mx, v[i]);
    }
#pragma unroll
    for (int o = 16; o > 0; o >>= 1)
        mx = fmaxf(mx, __shfl_xor_sync(0xffffffffu, mx, o));
    if ((t & 31) == 0) red[t >> 5] = mx;
    __syncthreads();
    mx = red[0];
#pragma unroll
    for (int w = 1; w < 8; w++) mx = fmaxf(mx, red[w]);

    float sum = 0.f;
#pragma unroll
    for (int i = 0; i < 8; i++) {
        v[i] = __expf(v[i] - mx);
        sum += v[i];
    }
#pragma unroll
    for (int o = 16; o > 0; o >>= 1)
        sum += __shfl_xor_sync(0xffffffffu, sum, o);
    __syncthreads();
    if ((t & 31) == 0) red[t >> 5] = sum;
    __syncthreads();
    sum = red[0];
#pragma unroll
    for (int w = 1; w < 8; w++) sum += red[w];

    float inv = 1.0f / sum;
#pragma unroll
    for (int i = 0; i < 8; i++) p[t + i * 256] = v[i] * inv;
}

// ---------------------------------------------------------------------------
extern "C" void kernel_launch(void* const* d_in, const int* in_sizes, int n_in,
                              void* d_out, int out_size)
{
    const float* q    = (const float*)d_in[0];
    const float* k    = (const float*)d_in[1];
    const float* v    = (const float*)d_in[2];
    const float* wq_w = (const float*)d_in[3];
    const float* wq_b = (const float*)d_in[4];
    const float* wk_w = (const float*)d_in[5];
    const float* wk_b = (const float*)d_in[6];
    const float* wv_w = (const float*)d_in[7];
    const float* wv_b = (const float*)d_in[8];
    const float* fc_w = (const float*)d_in[9];
    const float* fc_b = (const float*)d_in[10];

    float* out  = (float*)d_out;
    float* attn = out + (size_t)BB * SS * FF;   // out first, then attn

    float *qh, *kh, *vt, *ctx;
    cudaGetSymbolAddress((void**)&qh,  g_qh);
    cudaGetSymbolAddress((void**)&kh,  g_kh);
    cudaGetSymbolAddress((void**)&vt,  g_vt);
    cudaGetSymbolAddress((void**)&ctx, g_ctx);

    dim3 gProj(FF / 128, (BB * SS) / 128);     // (8, 64)
    mma_gemm<0><<<gProj, 256>>>(q, wq_w, wq_b, qh);
    mma_gemm<0><<<gProj, 256>>>(k, wk_w, wk_b, kh);
    mma_gemm<1><<<gProj, 256>>>(v, wv_w, wv_b, vt);

    dim3 gS(SS / 128, SS / 128, BB * HH);      // (16, 16, 64)
    mma_gemm<2><<<gS, 256>>>(qh, kh, nullptr, attn);

    softmax_kernel<<<(unsigned)((size_t)BB * HH * SS), 256>>>(attn);

    dim3 gC(1, SS / 128, BB * HH);             // (1, 16, 64)
    mma_gemm<3><<<gC, 256>>>(attn, vt, nullptr, ctx);

    mma_gemm<4><<<gProj, 256>>>(ctx, fc_w, fc_b, out);
}

// round 5
// speedup vs baseline: 2.5257x; 1.0941x over previous
#include <cuda_runtime.h>
#include <cuda_bf16.h>
#include <cstdint>

#define BB 4
#define SS 2048
#define FF 1024
#define HH 16
#define DD 64

// Scratch (allocation-free requirement -> __device__ globals)
__device__ float g_qh[BB*HH*SS*DD];   // [B,H,S,D]
__device__ float g_kh[BB*HH*SS*DD];   // [B,H,S,D]
__device__ float g_vt[BB*HH*DD*SS];   // [B,H,D,S]  (V transposed)
__device__ float g_ctx[BB*SS*FF];     // [B,S,F]

// ---------------------------------------------------------------------------
__device__ __forceinline__ uint32_t smem_u32(const void* p) {
    uint32_t a;
    asm("{ .reg .u64 t; cvta.to.shared.u64 t, %1; cvt.u32.u64 %0, t; }"
        : "=r"(a) : "l"(p));
    return a;
}

__device__ __forceinline__ void ldsm4(uint32_t* r, uint32_t addr) {
    asm volatile("ldmatrix.sync.aligned.m8n8.x4.shared.b16 {%0,%1,%2,%3}, [%4];"
                 : "=r"(r[0]), "=r"(r[1]), "=r"(r[2]), "=r"(r[3]) : "r"(addr));
}

__device__ __forceinline__ void mma16816(float* c, const uint32_t* a,
                                         uint32_t b0, uint32_t b1) {
    asm volatile(
        "mma.sync.aligned.m16n8k16.row.col.f32.bf16.bf16.f32 "
        "{%0,%1,%2,%3}, {%4,%5,%6,%7}, {%8,%9}, {%0,%1,%2,%3};"
        : "+f"(c[0]), "+f"(c[1]), "+f"(c[2]), "+f"(c[3])
        : "r"(a[0]), "r"(a[1]), "r"(a[2]), "r"(a[3]), "r"(b0), "r"(b1));
}

__device__ __forceinline__ uint32_t packbf(float a, float b) {
    __nv_bfloat162 t = __floats2bfloat162_rn(a, b);
    return *reinterpret_cast<uint32_t*>(&t);
}

// split float4 into bf16-hi pair-words and bf16-lo pair-words
__device__ __forceinline__ void split_pack(float4 v, uint2& hi, uint2& lo) {
    __nv_bfloat16 hx = __float2bfloat16(v.x);
    __nv_bfloat16 hy = __float2bfloat16(v.y);
    __nv_bfloat16 hz = __float2bfloat16(v.z);
    __nv_bfloat16 hw = __float2bfloat16(v.w);
    hi.x = packbf(v.x, v.y);
    hi.y = packbf(v.z, v.w);
    lo.x = packbf(v.x - __bfloat162float(hx), v.y - __bfloat162float(hy));
    lo.y = packbf(v.z - __bfloat162float(hz), v.w - __bfloat162float(hw));
}

// ---------------------------------------------------------------------------
// 3xBF16 mma.sync NT-GEMM.  STAGE:
//  0: proj Q/K : D[8192,1024] = A @ W^T + b -> split-head [B,H,S,D]
//  1: proj V   : same, written transposed [B,H,D,S]
//  2: scores   : per bh: D[2048,2048] = qh @ kh^T * 0.125
//  3: ctx      : per bh: D[2048,64] = attn @ vt^T -> ctx [B,S,F]
//  4: fc       : D[8192,1024] = ctx @ fcw^T + b, ReLU
// ---------------------------------------------------------------------------
template <int STAGE>
__global__ __launch_bounds__(256, 2) void mma_gemm(
    const float* __restrict__ A, const float* __restrict__ B,
    const float* __restrict__ bias, float* __restrict__ Dst)
{
    constexpr int NT   = (STAGE == 3) ? 64 : 128;
    constexpr int KTOT = (STAGE == 2) ? 64 : ((STAGE == 3) ? 2048 : 1024);
    constexpr int KC   = KTOT / 32;
    constexpr int LDA  = (STAGE == 2) ? 64 : ((STAGE == 3) ? 2048 : 1024);
    constexpr int LDB  = (STAGE == 2) ? 64 : ((STAGE == 3) ? 2048 : 1024);
    constexpr int WN     = NT / 2;       // cols per warp
    constexpr int NPAIRS = WN / 16;      // 4 or 2
    constexpr int NTILES = 2 * NPAIRS;   // 8 or 4
    constexpr int PAD = 40;              // halves per row (80B: conflict-free LDSM)

    __shared__ __align__(16) uint16_t As_h[128 * PAD];
    __shared__ __align__(16) uint16_t As_l[128 * PAD];
    __shared__ __align__(16) uint16_t Bs_h[NT * PAD];
    __shared__ __align__(16) uint16_t Bs_l[NT * PAD];

    const int tid  = threadIdx.x;
    const int wid  = tid >> 5;
    const int lane = tid & 31;
    const int warp_m = wid >> 1;
    const int warp_n = wid & 1;

    const int m0 = blockIdx.y * 128;
    const int n0 = blockIdx.x * NT;
    const int bh = blockIdx.z;

    const float* Ap;
    const float* Bp;
    if constexpr (STAGE == 2) {
        Ap = A + (size_t)bh * SS * DD + (size_t)m0 * LDA;
        Bp = B + (size_t)bh * SS * DD + (size_t)n0 * LDB;
    } else if constexpr (STAGE == 3) {
        Ap = A + (size_t)bh * SS * SS + (size_t)m0 * LDA;
        Bp = B + (size_t)bh * DD * SS;
    } else {
        Ap = A + (size_t)m0 * LDA;
        Bp = B + (size_t)n0 * LDB;
    }

    float acc[2][NTILES][4];
#pragma unroll
    for (int mt = 0; mt < 2; ++mt)
#pragma unroll
        for (int nt = 0; nt < NTILES; ++nt)
#pragma unroll
            for (int i = 0; i < 4; ++i) acc[mt][nt][i] = 0.f;

    for (int ch = 0; ch < KC; ++ch) {
        const int k0 = ch * 32;
        if (ch) __syncthreads();

        // ---- stage A tile: 128 rows x 32 f32 -> bf16 hi/lo ----
#pragma unroll
        for (int i = 0; i < 4; ++i) {
            int f = tid + i * 256;
            int r = f >> 3, c = (f & 7) << 2;
            float4 v = *(const float4*)(Ap + (size_t)r * LDA + k0 + c);
            uint2 hi, lo;
            split_pack(v, hi, lo);
            *(uint2*)&As_h[r * PAD + c] = hi;
            *(uint2*)&As_l[r * PAD + c] = lo;
        }
        // ---- stage B tile: NT rows x 32 f32 ----
#pragma unroll
        for (int i = 0; i < NT / 32; ++i) {
            int f = tid + i * 256;
            int r = f >> 3, c = (f & 7) << 2;
            float4 v = *(const float4*)(Bp + (size_t)r * LDB + k0 + c);
            uint2 hi, lo;
            split_pack(v, hi, lo);
            *(uint2*)&Bs_h[r * PAD + c] = hi;
            *(uint2*)&Bs_l[r * PAD + c] = lo;
        }
        __syncthreads();

#pragma unroll
        for (int ks = 0; ks < 2; ++ks) {
            const int kcol = ks * 16 + (lane >> 4) * 8;
            // ---- preload ALL fragments for this k-slice ----
            uint32_t ah[2][4], al[2][4];
#pragma unroll
            for (int mt = 0; mt < 2; ++mt) {
                int row = warp_m * 32 + mt * 16 + (lane & 15);
                ldsm4(ah[mt], smem_u32(&As_h[row * PAD + kcol]));
                ldsm4(al[mt], smem_u32(&As_l[row * PAD + kcol]));
            }
            uint32_t bhf[NPAIRS][4], blf[NPAIRS][4];
#pragma unroll
            for (int np = 0; np < NPAIRS; ++np) {
                int nrow = warp_n * WN + np * 16 + (lane & 15);
                ldsm4(bhf[np], smem_u32(&Bs_h[nrow * PAD + kcol]));
                ldsm4(blf[np], smem_u32(&Bs_l[nrow * PAD + kcol]));
            }
            // ---- term hh: all independent tiles back-to-back ----
#pragma unroll
            for (int mt = 0; mt < 2; ++mt)
#pragma unroll
                for (int np = 0; np < NPAIRS; ++np)
#pragma unroll
                    for (int sub = 0; sub < 2; ++sub)
                        mma16816(acc[mt][np * 2 + sub], ah[mt],
                                 bhf[np][sub], bhf[np][sub + 2]);
            // ---- term hl ----
#pragma unroll
            for (int mt = 0; mt < 2; ++mt)
#pragma unroll
                for (int np = 0; np < NPAIRS; ++np)
#pragma unroll
                    for (int sub = 0; sub < 2; ++sub)
                        mma16816(acc[mt][np * 2 + sub], ah[mt],
                                 blf[np][sub], blf[np][sub + 2]);
            // ---- term lh ----
#pragma unroll
            for (int mt = 0; mt < 2; ++mt)
#pragma unroll
                for (int np = 0; np < NPAIRS; ++np)
#pragma unroll
                    for (int sub = 0; sub < 2; ++sub)
                        mma16816(acc[mt][np * 2 + sub], al[mt],
                                 bhf[np][sub], bhf[np][sub + 2]);
        }
    }

    // ---- epilogue ----
    const int g = lane >> 2;
    const int j = (lane & 3) << 1;
    const int m_base = m0 + warp_m * 32;
    const int n_base = n0 + warp_n * WN;

#pragma unroll
    for (int mt = 0; mt < 2; ++mt) {
#pragma unroll
        for (int nt = 0; nt < NTILES; ++nt) {
#pragma unroll
            for (int e = 0; e < 4; ++e) {
                int row = m_base + mt * 16 + g + (e >> 1) * 8;
                int col = n_base + nt * 8 + j + (e & 1);
                float val = acc[mt][nt][e];
                if constexpr (STAGE == 0) {
                    val += bias[col];
                    int b = row >> 11, s = row & 2047, h = col >> 6, d = col & 63;
                    Dst[((((size_t)b * HH + h) * SS) + s) * DD + d] = val;
                } else if constexpr (STAGE == 1) {
                    val += bias[col];
                    int b = row >> 11, s = row & 2047, h = col >> 6, d = col & 63;
                    Dst[((((size_t)b * HH + h) * DD) + d) * SS + s] = val;
                } else if constexpr (STAGE == 2) {
                    Dst[((size_t)bh * SS + row) * SS + col] = val * 0.125f;
                } else if constexpr (STAGE == 3) {
                    int b = bh >> 4, h = bh & 15, s = row;
                    Dst[((size_t)b * SS + s) * FF + h * DD + col] = val;
                } else {
                    val += bias[col];
                    Dst[(size_t)row * FF + col] = fmaxf(val, 0.f);
                }
            }
        }
    }
}

// ---------------------------------------------------------------------------
// In-place row softmax over rows of length 2048, float4-vectorized.
// One block (256 thr) per row; each thread owns 2 float4 (8 elems).
// ---------------------------------------------------------------------------
__global__ __launch_bounds__(256) void softmax_kernel(float* __restrict__ attn)
{
    const size_t row = blockIdx.x;
    float4* p4 = (float4*)(attn + row * SS);
    const int t = threadIdx.x;
    __shared__ float red[8];

    float4 v[2];
    float mx = -1e30f;
#pragma unroll
    for (int i = 0; i < 2; i++) {
        v[i] = p4[t + i * 256];
        mx = fmaxf(mx, fmaxf(fmaxf(v[i].x, v[i].y), fmaxf(v[i].z, v[i].w)));
    }
#pragma unroll
    for (int o = 16; o > 0; o >>= 1)
        mx = fmaxf(mx, __shfl_xor_sync(0xffffffffu, mx, o));
    if ((t & 31) == 0) red[t >> 5] = mx;
    __syncthreads();
    mx = red[0];
#pragma unroll
    for (int w = 1; w < 8; w++) mx = fmaxf(mx, red[w]);

    float sum = 0.f;
#pragma unroll
    for (int i = 0; i < 2; i++) {
        v[i].x = __expf(v[i].x - mx);
        v[i].y = __expf(v[i].y - mx);
        v[i].z = __expf(v[i].z - mx);
        v[i].w = __expf(v[i].w - mx);
        sum += (v[i].x + v[i].y) + (v[i].z + v[i].w);
    }
#pragma unroll
    for (int o = 16; o > 0; o >>= 1)
        sum += __shfl_xor_sync(0xffffffffu, sum, o);
    __syncthreads();
    if ((t & 31) == 0) red[t >> 5] = sum;
    __syncthreads();
    sum = red[0];
#pragma unroll
    for (int w = 1; w < 8; w++) sum += red[w];

    float inv = 1.0f / sum;
#pragma unroll
    for (int i = 0; i < 2; i++) {
        v[i].x *= inv; v[i].y *= inv; v[i].z *= inv; v[i].w *= inv;
        p4[t + i * 256] = v[i];
    }
}

// ---------------------------------------------------------------------------
extern "C" void kernel_launch(void* const* d_in, const int* in_sizes, int n_in,
                              void* d_out, int out_size)
{
    const float* q    = (const float*)d_in[0];
    const float* k    = (const float*)d_in[1];
    const float* v    = (const float*)d_in[2];
    const float* wq_w = (const float*)d_in[3];
    const float* wq_b = (const float*)d_in[4];
    const float* wk_w = (const float*)d_in[5];
    const float* wk_b = (const float*)d_in[6];
    const float* wv_w = (const float*)d_in[7];
    const float* wv_b = (const float*)d_in[8];
    const float* fc_w = (const float*)d_in[9];
    const float* fc_b = (const float*)d_in[10];

    float* out  = (float*)d_out;
    float* attn = out + (size_t)BB * SS * FF;   // out first, then attn

    float *qh, *kh, *vt, *ctx;
    cudaGetSymbolAddress((void**)&qh,  g_qh);
    cudaGetSymbolAddress((void**)&kh,  g_kh);
    cudaGetSymbolAddress((void**)&vt,  g_vt);
    cudaGetSymbolAddress((void**)&ctx, g_ctx);

    dim3 gProj(FF / 128, (BB * SS) / 128);     // (8, 64)
    mma_gemm<0><<<gProj, 256>>>(q, wq_w, wq_b, qh);
    mma_gemm<0><<<gProj, 256>>>(k, wk_w, wk_b, kh);
    mma_gemm<1><<<gProj, 256>>>(v, wv_w, wv_b, vt);

    dim3 gS(SS / 128, SS / 128, BB * HH);      // (16, 16, 64)
    mma_gemm<2><<<gS, 256>>>(qh, kh, nullptr, attn);

    softmax_kernel<<<(unsigned)((size_t)BB * HH * SS), 256>>>(attn);

    dim3 gC(1, SS / 128, BB * HH);             // (1, 16, 64)
    mma_gemm<3><<<gC, 256>>>(attn, vt, nullptr, ctx);

    mma_gemm<4><<<gProj, 256>>>(ctx, fc_w, fc_b, out);
}